// round 9
// baseline (speedup 1.0000x reference)
#include <cuda_runtime.h>
#include <cmath>

#define HID  640
#define ADIM 128
#define WPB  144     // warp-partials per batch; 18 blocks/batch -> 288 blocks
#define BPB  18      // blocks per batch (batch-pure blocks)
#define MAXB 16

// ---- device scratch (no allocations allowed) ----
__device__ float g_q[MAXB * ADIM];
__device__ float g_r[MAXB * HID];
__device__ float g_pacc[(size_t)MAXB * WPB * HID];   // 5.9 MB
__device__ float g_pm[MAXB * WPB];
__device__ float g_ps[MAXB * WPB];
__device__ float g_pooled[MAXB * HID];
__device__ float g_y[MAXB * HID];

// ---------------------------------------------------------------------------
// Kernel 1a: q[b,a] = dot(Wq[a,:], pos[b,:])   — one warp per output
// ---------------------------------------------------------------------------
__global__ void __launch_bounds__(256) k_q(const float* __restrict__ pos,
                                           const float* __restrict__ Wq) {
    int gw   = blockIdx.x * 8 + (threadIdx.x >> 5);
    int lane = threadIdx.x & 31;
    int b = gw >> 7;
    int a = gw & 127;

    const float* wr = Wq + (size_t)a * HID;
    const float* pr = pos + (size_t)b * HID;
    float s = 0.f;
    #pragma unroll
    for (int k = 0; k < HID / 32; k++) {
        int h = lane + 32 * k;
        s += wr[h] * pr[h];
    }
    #pragma unroll
    for (int o = 16; o > 0; o >>= 1) s += __shfl_xor_sync(0xffffffffu, s, o);
    if (lane == 0) g_q[b * ADIM + a] = s;
}

// ---------------------------------------------------------------------------
// Kernel 1b: r[b,h] = scale * sum_a Wk[a,h] * q[b,a]
// ---------------------------------------------------------------------------
__global__ void __launch_bounds__(160) k_r(const float* __restrict__ Wk,
                                           float scale) {
    int b = blockIdx.x;
    int h = blockIdx.y * 160 + threadIdx.x;

    __shared__ float qs[ADIM];
    if (threadIdx.x < ADIM) qs[threadIdx.x] = g_q[b * ADIM + threadIdx.x];
    __syncthreads();

    float s = 0.f;
    #pragma unroll 8
    for (int a = 0; a < ADIM; a++) s += Wk[(size_t)a * HID + h] * qs[a];
    g_r[b * HID + h] = s * scale;
}

// ---------------------------------------------------------------------------
// Kernel 2: streaming pass over gene_hiddens (819 MB), 3-ROW pipeline:
// 15 float4 loads in flight per warp per iteration. r vector lives in
// SHARED (batch-pure blocks) to keep regs ~100 -> no spill at 2 blocks/SM.
// ---------------------------------------------------------------------------
__global__ void __launch_bounds__(256, 2) k_pass1(const float* __restrict__ gh,
                                                  int N) {
    int b    = blockIdx.x / BPB;
    int c    = blockIdx.x % BPB;
    int warp = threadIdx.x >> 5;
    int lane = threadIdx.x & 31;
    int w    = c * 8 + warp;              // 0..143

    __shared__ float4 srr[HID / 4];       // 2.5 KB
    if (threadIdx.x < HID / 4)
        srr[threadIdx.x] = reinterpret_cast<const float4*>(g_r + b * HID)[threadIdx.x];
    __syncthreads();

    int rpw = (N + WPB - 1) / WPB;        // 139
    int n0  = w * rpw;
    int n1  = min(N, n0 + rpw);

    float4 acc[5];
    #pragma unroll
    for (int k = 0; k < 5; k++) acc[k] = make_float4(0.f, 0.f, 0.f, 0.f);

    float m = -1e30f, s = 0.f;
    const float4* base = reinterpret_cast<const float4*>(gh) + (size_t)b * N * (HID / 4);

    int n = n0;
    int head = (n1 - n0) % 3;
    for (int i = 0; i < head; i++, n++) {
        const float4* p = base + (size_t)n * (HID / 4);
        float4 hv[5];
        #pragma unroll
        for (int k = 0; k < 5; k++) hv[k] = __ldcs(p + lane + 32 * k);
        float d = 0.f;
        #pragma unroll
        for (int k = 0; k < 5; k++) {
            float4 r = srr[lane + 32 * k];
            d += hv[k].x * r.x + hv[k].y * r.y + hv[k].z * r.z + hv[k].w * r.w;
        }
        #pragma unroll
        for (int o = 16; o > 0; o >>= 1) d += __shfl_xor_sync(0xffffffffu, d, o);
        if (d > m) {
            float cc = __expf(m - d);
            s *= cc;
            #pragma unroll
            for (int k = 0; k < 5; k++) {
                acc[k].x *= cc; acc[k].y *= cc; acc[k].z *= cc; acc[k].w *= cc;
            }
            m = d;
        }
        float wt = __expf(d - m);
        s += wt;
        #pragma unroll
        for (int k = 0; k < 5; k++) {
            acc[k].x += wt * hv[k].x; acc[k].y += wt * hv[k].y;
            acc[k].z += wt * hv[k].z; acc[k].w += wt * hv[k].w;
        }
    }

    for (; n < n1; n += 3) {
        const float4* p0 = base + (size_t)n * (HID / 4);
        float4 h0[5], h1[5], h2[5];
        #pragma unroll
        for (int k = 0; k < 5; k++) h0[k] = __ldcs(p0 + lane + 32 * k);
        #pragma unroll
        for (int k = 0; k < 5; k++) h1[k] = __ldcs(p0 + (HID / 4) + lane + 32 * k);
        #pragma unroll
        for (int k = 0; k < 5; k++) h2[k] = __ldcs(p0 + 2 * (HID / 4) + lane + 32 * k);

        float d0 = 0.f, d1 = 0.f, d2 = 0.f;
        #pragma unroll
        for (int k = 0; k < 5; k++) {
            float4 r = srr[lane + 32 * k];
            d0 += h0[k].x * r.x + h0[k].y * r.y + h0[k].z * r.z + h0[k].w * r.w;
            d1 += h1[k].x * r.x + h1[k].y * r.y + h1[k].z * r.z + h1[k].w * r.w;
            d2 += h2[k].x * r.x + h2[k].y * r.y + h2[k].z * r.z + h2[k].w * r.w;
        }
        #pragma unroll
        for (int o = 16; o > 0; o >>= 1) {
            d0 += __shfl_xor_sync(0xffffffffu, d0, o);
            d1 += __shfl_xor_sync(0xffffffffu, d1, o);
            d2 += __shfl_xor_sync(0xffffffffu, d2, o);
        }

        float mn = fmaxf(fmaxf(d0, d1), d2);
        if (mn > m) {                      // warp-uniform
            float cc = __expf(m - mn);
            s *= cc;
            #pragma unroll
            for (int k = 0; k < 5; k++) {
                acc[k].x *= cc; acc[k].y *= cc; acc[k].z *= cc; acc[k].w *= cc;
            }
            m = mn;
        }
        float w0 = __expf(d0 - m);
        float w1 = __expf(d1 - m);
        float w2 = __expf(d2 - m);
        s += w0 + w1 + w2;
        #pragma unroll
        for (int k = 0; k < 5; k++) {
            acc[k].x += w0 * h0[k].x + w1 * h1[k].x + w2 * h2[k].x;
            acc[k].y += w0 * h0[k].y + w1 * h1[k].y + w2 * h2[k].y;
            acc[k].z += w0 * h0[k].z + w1 * h1[k].z + w2 * h2[k].z;
            acc[k].w += w0 * h0[k].w + w1 * h1[k].w + w2 * h2[k].w;
        }
    }

    float4* pa = reinterpret_cast<float4*>(g_pacc + (size_t)(b * WPB + w) * HID);
    #pragma unroll
    for (int k = 0; k < 5; k++) pa[lane + 32 * k] = acc[k];
    if (lane == 0) { g_pm[b * WPB + w] = m; g_ps[b * WPB + w] = s; }
}

// ---------------------------------------------------------------------------
// Kernel 3: pooled[b,h] = invS * sum_i wsm[i] * pacc[b,i,h]
// grid (B, 20) x 256: 32 h per block, 8 threads per h (18 partials each).
// wsm/M/S recomputed redundantly per block (wide + cheap).
// ---------------------------------------------------------------------------
__global__ void __launch_bounds__(256) k_pooled(int dummy) {
    int b = blockIdx.x;
    int t = threadIdx.x;
    int lane = t & 31, wid = t >> 5;

    __shared__ float wsm[WPB];
    __shared__ float sred[8];
    __shared__ float sInvS;

    float pm = (t < WPB) ? g_pm[b * WPB + t] : -1e30f;
    float ps = (t < WPB) ? g_ps[b * WPB + t] : 0.f;

    float mv = pm;
    #pragma unroll
    for (int o = 16; o > 0; o >>= 1)
        mv = fmaxf(mv, __shfl_xor_sync(0xffffffffu, mv, o));
    if (lane == 0) sred[wid] = mv;
    __syncthreads();
    float M = sred[0];
    #pragma unroll
    for (int i = 1; i < 8; i++) M = fmaxf(M, sred[i]);
    __syncthreads();

    float w = (t < WPB) ? __expf(pm - M) : 0.f;
    if (t < WPB) wsm[t] = w;
    float sv = w * ps;
    #pragma unroll
    for (int o = 16; o > 0; o >>= 1) sv += __shfl_xor_sync(0xffffffffu, sv, o);
    if (lane == 0) sred[wid] = sv;
    __syncthreads();
    if (t == 0) {
        float S = 0.f;
        #pragma unroll
        for (int i = 0; i < 8; i++) S += sred[i];
        sInvS = 1.f / S;
    }
    __syncthreads();

    // 8 threads per h, 18 partials each
    int h = blockIdx.y * 32 + (t & 31);
    int q = t >> 5;                        // 0..7
    const float* pa = g_pacc + (size_t)b * WPB * HID + h;

    float a = 0.f;
    int i0 = q * 18;
    #pragma unroll
    for (int i = i0; i < i0 + 18; i++)
        a += wsm[i] * pa[(size_t)i * HID];

    __shared__ float red[256];
    red[t] = a;
    __syncthreads();
    if (q == 0) {
        float tot = a;
        #pragma unroll
        for (int i = 1; i < 8; i++) tot += red[t + 32 * i];
        g_pooled[b * HID + h] = tot * sInvS;
    }
}

// ---------------------------------------------------------------------------
// Kernel 4: y[b,v] = dot(Wv[v,:], pooled[b,:])
// one warp per (b,v); v-major so 16 warps share each Wv row.
// ---------------------------------------------------------------------------
__global__ void __launch_bounds__(256) k_y(const float* __restrict__ Wv) {
    int gw   = blockIdx.x * 8 + (threadIdx.x >> 5);
    int lane = threadIdx.x & 31;
    int v = gw >> 4;
    int b = gw & 15;

    const float* wr = Wv + (size_t)v * HID;
    const float* pr = g_pooled + (size_t)b * HID;
    float s = 0.f;
    #pragma unroll
    for (int k = 0; k < HID / 32; k++) {
        int h = lane + 32 * k;
        s += wr[h] * pr[h];
    }
    #pragma unroll
    for (int o = 16; o > 0; o >>= 1) s += __shfl_xor_sync(0xffffffffu, s, o);
    if (lane == 0) g_y[b * HID + v] = s;
}

// ---------------------------------------------------------------------------
// Kernel 5: LayerNorm over 640. grid=B, block=640.
// ---------------------------------------------------------------------------
__device__ __forceinline__ float block_sum_640(float v, float* sred, int t) {
    int lane = t & 31, wid = t >> 5;
    #pragma unroll
    for (int o = 16; o > 0; o >>= 1) v += __shfl_xor_sync(0xffffffffu, v, o);
    if (lane == 0) sred[wid] = v;
    __syncthreads();
    if (wid == 0) {
        float x = (lane < 20) ? sred[lane] : 0.f;
        #pragma unroll
        for (int o = 16; o > 0; o >>= 1) x += __shfl_xor_sync(0xffffffffu, x, o);
        if (lane == 0) sred[0] = x;
    }
    __syncthreads();
    float r = sred[0];
    __syncthreads();
    return r;
}

__global__ void __launch_bounds__(640) k_ln(const float* __restrict__ gamma,
                                            const float* __restrict__ beta,
                                            float* __restrict__ out) {
    int b = blockIdx.x;
    int t = threadIdx.x;
    __shared__ float sred[32];

    float x = g_y[b * HID + t];
    float mean = block_sum_640(x, sred, t) * (1.f / HID);
    float dx = x - mean;
    float var = block_sum_640(dx * dx, sred, t) * (1.f / HID);
    out[b * HID + t] = dx * rsqrtf(var + 1e-5f) * gamma[t] + beta[t];
}

// ---------------------------------------------------------------------------
extern "C" void kernel_launch(void* const* d_in, const int* in_sizes, int n_in,
                              void* d_out, int out_size) {
    const float* gh    = (const float*)d_in[0];
    const float* pos   = (const float*)d_in[1];
    const float* Wq    = (const float*)d_in[2];
    const float* Wk    = (const float*)d_in[3];
    const float* Wv    = (const float*)d_in[4];
    const float* gamma = (const float*)d_in[5];
    const float* beta  = (const float*)d_in[6];
    float* out = (float*)d_out;

    int B = in_sizes[1] / HID;             // 16
    int N = in_sizes[0] / (B * HID);       // 20000
    float scale = 1.0f / sqrtf((float)ADIM);

    k_q<<<(B * ADIM) / 8, 256>>>(pos, Wq);            // 256 blocks
    k_r<<<dim3(B, HID / 160), 160>>>(Wk, scale);      // 64 blocks

    k_pass1<<<B * BPB, 256>>>(gh, N);                 // 288 blocks = 2/SM

    k_pooled<<<dim3(B, 20), 256>>>(0);                // 320 blocks
    k_y<<<(B * HID) / 8, 256>>>(Wv);                  // 1280 blocks
    k_ln<<<B, HID>>>(gamma, beta, out);
}

// round 10
// speedup vs baseline: 1.0014x; 1.0014x over previous
#include <cuda_runtime.h>
#include <cmath>

#define HID  640
#define ADIM 128
#define BPB  27      // batch-pure blocks per batch -> 432 blocks <= 3/SM * 148
#define WPB  (BPB*8) // 216 warp-partials per batch
#define MAXB 16

// ---- device scratch (no allocations allowed) ----
__device__ float g_q[MAXB * ADIM];
__device__ float g_r[MAXB * HID];
__device__ float g_pacc[(size_t)MAXB * WPB * HID];   // 8.8 MB
__device__ float g_pm[MAXB * WPB];
__device__ float g_ps[MAXB * WPB];
__device__ float g_pooled[MAXB * HID];
__device__ float g_y[MAXB * HID];

// ---------------------------------------------------------------------------
// Kernel 1a: q[b,a] = dot(Wq[a,:], pos[b,:])   — one warp per output
// ---------------------------------------------------------------------------
__global__ void __launch_bounds__(256) k_q(const float* __restrict__ pos,
                                           const float* __restrict__ Wq) {
    int gw   = blockIdx.x * 8 + (threadIdx.x >> 5);
    int lane = threadIdx.x & 31;
    int b = gw >> 7;
    int a = gw & 127;

    const float* wr = Wq + (size_t)a * HID;
    const float* pr = pos + (size_t)b * HID;
    float s = 0.f;
    #pragma unroll
    for (int k = 0; k < HID / 32; k++) {
        int h = lane + 32 * k;
        s += wr[h] * pr[h];
    }
    #pragma unroll
    for (int o = 16; o > 0; o >>= 1) s += __shfl_xor_sync(0xffffffffu, s, o);
    if (lane == 0) g_q[b * ADIM + a] = s;
}

// ---------------------------------------------------------------------------
// Kernel 1b: r[b,h] = scale * sum_a Wk[a,h] * q[b,a]
// ---------------------------------------------------------------------------
__global__ void __launch_bounds__(160) k_r(const float* __restrict__ Wk,
                                           float scale) {
    int b = blockIdx.x;
    int h = blockIdx.y * 160 + threadIdx.x;

    __shared__ float qs[ADIM];
    if (threadIdx.x < ADIM) qs[threadIdx.x] = g_q[b * ADIM + threadIdx.x];
    __syncthreads();

    float s = 0.f;
    #pragma unroll 8
    for (int a = 0; a < ADIM; a++) s += Wk[(size_t)a * HID + h] * qs[a];
    g_r[b * HID + h] = s * scale;
}

// ---------------------------------------------------------------------------
// Kernel 2: streaming pass over gene_hiddens (819 MB). 2-ROW pipeline
// (10 float4 in flight/warp) + r in SHARED (saves 20 regs) -> ~80 regs
// -> 3 blocks/SM (24 warps) for deeper chip-level MLP.
// ---------------------------------------------------------------------------
__global__ void __launch_bounds__(256, 3) k_pass1(const float* __restrict__ gh,
                                                  int N) {
    int b    = blockIdx.x / BPB;
    int c    = blockIdx.x % BPB;
    int warp = threadIdx.x >> 5;
    int lane = threadIdx.x & 31;
    int w    = c * 8 + warp;              // 0..215

    __shared__ float4 srr[HID / 4];       // 2.5 KB
    if (threadIdx.x < HID / 4)
        srr[threadIdx.x] = reinterpret_cast<const float4*>(g_r + b * HID)[threadIdx.x];
    __syncthreads();

    int rpw = (N + WPB - 1) / WPB;        // 93
    int n0  = w * rpw;
    int n1  = min(N, n0 + rpw);

    float4 acc[5];
    #pragma unroll
    for (int k = 0; k < 5; k++) acc[k] = make_float4(0.f, 0.f, 0.f, 0.f);

    float m = -1e30f, s = 0.f;
    const float4* base = reinterpret_cast<const float4*>(gh) + (size_t)b * N * (HID / 4);

    int n = n0;
    if (n < n1 && ((n1 - n0) & 1)) {      // odd head: single row
        const float4* p = base + (size_t)n * (HID / 4);
        float4 hv[5];
        #pragma unroll
        for (int k = 0; k < 5; k++) hv[k] = __ldcs(p + lane + 32 * k);
        float d = 0.f;
        #pragma unroll
        for (int k = 0; k < 5; k++) {
            float4 r = srr[lane + 32 * k];
            d += hv[k].x * r.x + hv[k].y * r.y + hv[k].z * r.z + hv[k].w * r.w;
        }
        #pragma unroll
        for (int o = 16; o > 0; o >>= 1) d += __shfl_xor_sync(0xffffffffu, d, o);
        m = d; s = 1.f;
        #pragma unroll
        for (int k = 0; k < 5; k++) acc[k] = hv[k];
        n++;
    }

    for (; n < n1; n += 2) {
        const float4* p0 = base + (size_t)n * (HID / 4);
        const float4* p1 = p0 + (HID / 4);
        float4 h0[5], h1[5];
        #pragma unroll
        for (int k = 0; k < 5; k++) h0[k] = __ldcs(p0 + lane + 32 * k);
        #pragma unroll
        for (int k = 0; k < 5; k++) h1[k] = __ldcs(p1 + lane + 32 * k);

        float d0 = 0.f, d1 = 0.f;
        #pragma unroll
        for (int k = 0; k < 5; k++) {
            float4 r = srr[lane + 32 * k];
            d0 += h0[k].x * r.x + h0[k].y * r.y + h0[k].z * r.z + h0[k].w * r.w;
            d1 += h1[k].x * r.x + h1[k].y * r.y + h1[k].z * r.z + h1[k].w * r.w;
        }
        #pragma unroll
        for (int o = 16; o > 0; o >>= 1) {
            d0 += __shfl_xor_sync(0xffffffffu, d0, o);
            d1 += __shfl_xor_sync(0xffffffffu, d1, o);
        }

        float mn = fmaxf(d0, d1);
        if (mn > m) {                      // warp-uniform
            float cc = __expf(m - mn);
            s *= cc;
            #pragma unroll
            for (int k = 0; k < 5; k++) {
                acc[k].x *= cc; acc[k].y *= cc; acc[k].z *= cc; acc[k].w *= cc;
            }
            m = mn;
        }
        float w0 = __expf(d0 - m);
        float w1 = __expf(d1 - m);
        s += w0 + w1;
        #pragma unroll
        for (int k = 0; k < 5; k++) {
            acc[k].x += w0 * h0[k].x + w1 * h1[k].x;
            acc[k].y += w0 * h0[k].y + w1 * h1[k].y;
            acc[k].z += w0 * h0[k].z + w1 * h1[k].z;
            acc[k].w += w0 * h0[k].w + w1 * h1[k].w;
        }
    }

    float4* pa = reinterpret_cast<float4*>(g_pacc + (size_t)(b * WPB + w) * HID);
    #pragma unroll
    for (int k = 0; k < 5; k++) pa[lane + 32 * k] = acc[k];
    if (lane == 0) { g_pm[b * WPB + w] = m; g_ps[b * WPB + w] = s; }
}

// ---------------------------------------------------------------------------
// Kernel 3: pooled[b,h] = invS * sum_i wsm[i] * pacc[b,i,h]
// grid (B, 20) x 256: 32 h per block, 8 threads per h (27 partials each).
// wsm/M/S recomputed redundantly per block (wide + cheap).
// ---------------------------------------------------------------------------
__global__ void __launch_bounds__(256) k_pooled(int dummy) {
    int b = blockIdx.x;
    int t = threadIdx.x;
    int lane = t & 31, wid = t >> 5;

    __shared__ float wsm[WPB];
    __shared__ float sred[8];
    __shared__ float sInvS;

    float pm = (t < WPB) ? g_pm[b * WPB + t] : -1e30f;
    float ps = (t < WPB) ? g_ps[b * WPB + t] : 0.f;

    float mv = pm;
    #pragma unroll
    for (int o = 16; o > 0; o >>= 1)
        mv = fmaxf(mv, __shfl_xor_sync(0xffffffffu, mv, o));
    if (lane == 0) sred[wid] = mv;
    __syncthreads();
    float M = sred[0];
    #pragma unroll
    for (int i = 1; i < 8; i++) M = fmaxf(M, sred[i]);
    __syncthreads();

    float w = (t < WPB) ? __expf(pm - M) : 0.f;
    if (t < WPB) wsm[t] = w;
    float sv = w * ps;
    #pragma unroll
    for (int o = 16; o > 0; o >>= 1) sv += __shfl_xor_sync(0xffffffffu, sv, o);
    if (lane == 0) sred[wid] = sv;
    __syncthreads();
    if (t == 0) {
        float S = 0.f;
        #pragma unroll
        for (int i = 0; i < 8; i++) S += sred[i];
        sInvS = 1.f / S;
    }
    __syncthreads();

    // 8 threads per h, 27 partials each
    int h = blockIdx.y * 32 + (t & 31);
    int q = t >> 5;                        // 0..7
    const float* pa = g_pacc + (size_t)b * WPB * HID + h;

    float a = 0.f;
    int i0 = q * 27;
    #pragma unroll
    for (int i = i0; i < i0 + 27; i++)
        a += wsm[i] * pa[(size_t)i * HID];

    __shared__ float red[256];
    red[t] = a;
    __syncthreads();
    if (q == 0) {
        float tot = a;
        #pragma unroll
        for (int i = 1; i < 8; i++) tot += red[t + 32 * i];
        g_pooled[b * HID + h] = tot * sInvS;
    }
}

// ---------------------------------------------------------------------------
// Kernel 4: y[b,v] = dot(Wv[v,:], pooled[b,:])
// one warp per (b,v); v-major so 16 warps share each Wv row.
// ---------------------------------------------------------------------------
__global__ void __launch_bounds__(256) k_y(const float* __restrict__ Wv) {
    int gw   = blockIdx.x * 8 + (threadIdx.x >> 5);
    int lane = threadIdx.x & 31;
    int v = gw >> 4;
    int b = gw & 15;

    const float* wr = Wv + (size_t)v * HID;
    const float* pr = g_pooled + (size_t)b * HID;
    float s = 0.f;
    #pragma unroll
    for (int k = 0; k < HID / 32; k++) {
        int h = lane + 32 * k;
        s += wr[h] * pr[h];
    }
    #pragma unroll
    for (int o = 16; o > 0; o >>= 1) s += __shfl_xor_sync(0xffffffffu, s, o);
    if (lane == 0) g_y[b * HID + v] = s;
}

// ---------------------------------------------------------------------------
// Kernel 5: LayerNorm over 640. grid=B, block=640.
// ---------------------------------------------------------------------------
__device__ __forceinline__ float block_sum_640(float v, float* sred, int t) {
    int lane = t & 31, wid = t >> 5;
    #pragma unroll
    for (int o = 16; o > 0; o >>= 1) v += __shfl_xor_sync(0xffffffffu, v, o);
    if (lane == 0) sred[wid] = v;
    __syncthreads();
    if (wid == 0) {
        float x = (lane < 20) ? sred[lane] : 0.f;
        #pragma unroll
        for (int o = 16; o > 0; o >>= 1) x += __shfl_xor_sync(0xffffffffu, x, o);
        if (lane == 0) sred[0] = x;
    }
    __syncthreads();
    float r = sred[0];
    __syncthreads();
    return r;
}

__global__ void __launch_bounds__(640) k_ln(const float* __restrict__ gamma,
                                            const float* __restrict__ beta,
                                            float* __restrict__ out) {
    int b = blockIdx.x;
    int t = threadIdx.x;
    __shared__ float sred[32];

    float x = g_y[b * HID + t];
    float mean = block_sum_640(x, sred, t) * (1.f / HID);
    float dx = x - mean;
    float var = block_sum_640(dx * dx, sred, t) * (1.f / HID);
    out[b * HID + t] = dx * rsqrtf(var + 1e-5f) * gamma[t] + beta[t];
}

// ---------------------------------------------------------------------------
extern "C" void kernel_launch(void* const* d_in, const int* in_sizes, int n_in,
                              void* d_out, int out_size) {
    const float* gh    = (const float*)d_in[0];
    const float* pos   = (const float*)d_in[1];
    const float* Wq    = (const float*)d_in[2];
    const float* Wk    = (const float*)d_in[3];
    const float* Wv    = (const float*)d_in[4];
    const float* gamma = (const float*)d_in[5];
    const float* beta  = (const float*)d_in[6];
    float* out = (float*)d_out;

    int B = in_sizes[1] / HID;             // 16
    int N = in_sizes[0] / (B * HID);       // 20000
    float scale = 1.0f / sqrtf((float)ADIM);

    k_q<<<(B * ADIM) / 8, 256>>>(pos, Wq);            // 256 blocks
    k_r<<<dim3(B, HID / 160), 160>>>(Wk, scale);      // 64 blocks

    k_pass1<<<B * BPB, 256>>>(gh, N);                 // 432 blocks = 3/SM

    k_pooled<<<dim3(B, 20), 256>>>(0);                // 320 blocks
    k_y<<<(B * HID) / 8, 256>>>(Wv);                  // 1280 blocks
    k_ln<<<B, HID>>>(gamma, beta, out);
}

// round 11
// speedup vs baseline: 1.0447x; 1.0433x over previous
#include <cuda_runtime.h>
#include <cmath>

#define HID  640
#define ADIM 128
#define WPB  148     // warp-partials per batch -> 2368 warps = 296 blocks = 2/SM
#define MAXB 16

// ---- device scratch (no allocations allowed) ----
__device__ float g_q[MAXB * ADIM];
__device__ float g_r[MAXB * HID];
__device__ float g_pacc[(size_t)MAXB * WPB * HID];  // 6 MB
__device__ float g_pm[MAXB * WPB];
__device__ float g_ps[MAXB * WPB];
__device__ float g_pooled[MAXB * HID];
__device__ float g_y[MAXB * HID];

// ---------------------------------------------------------------------------
// Kernel 1a: q[b,a] = dot(Wq[a,:], pos[b,:])   — one warp per output
// ---------------------------------------------------------------------------
__global__ void __launch_bounds__(256) k_q(const float* __restrict__ pos,
                                           const float* __restrict__ Wq) {
    int gw   = blockIdx.x * 8 + (threadIdx.x >> 5);
    int lane = threadIdx.x & 31;
    int b = gw >> 7;
    int a = gw & 127;

    const float* wr = Wq + (size_t)a * HID;
    const float* pr = pos + (size_t)b * HID;
    float s = 0.f;
    #pragma unroll
    for (int k = 0; k < HID / 32; k++) {
        int h = lane + 32 * k;
        s += wr[h] * pr[h];
    }
    #pragma unroll
    for (int o = 16; o > 0; o >>= 1) s += __shfl_xor_sync(0xffffffffu, s, o);
    if (lane == 0) g_q[b * ADIM + a] = s;
}

// ---------------------------------------------------------------------------
// Kernel 1b: r[b,h] = scale * sum_a Wk[a,h] * q[b,a]
// grid (B,5) x 512: 128 h per block, 4 threads per h (32 a's each, deep MLP)
// ---------------------------------------------------------------------------
__global__ void __launch_bounds__(512) k_r(const float* __restrict__ Wk,
                                           float scale) {
    int b = blockIdx.x;
    int t = threadIdx.x;
    int h = blockIdx.y * 128 + (t & 127);
    int q = t >> 7;                       // 0..3

    __shared__ float qs[ADIM];
    if (t < ADIM) qs[t] = g_q[b * ADIM + t];
    __syncthreads();

    float s = 0.f;
    int a0 = q * 32;
    #pragma unroll
    for (int a = 0; a < 32; a++)
        s += Wk[(size_t)(a0 + a) * HID + h] * qs[a0 + a];

    __shared__ float red[512];
    red[t] = s;
    __syncthreads();
    if (q == 0)
        g_r[b * HID + h] = (s + red[t + 128] + red[t + 256] + red[t + 384]) * scale;
}

// ---------------------------------------------------------------------------
// Kernel 2: streaming pass over gene_hiddens (819 MB), 2-ROW pipeline:
// 10 float4 loads in flight per warp per iteration, interleaved shfl trees.
// 2 blocks/SM, ~100 regs (no spill). [R8-proven configuration]
// ---------------------------------------------------------------------------
__global__ void __launch_bounds__(256, 2) k_pass1(const float* __restrict__ gh,
                                                  int B, int N) {
    int wg   = blockIdx.x * 8 + (threadIdx.x >> 5);
    int b    = wg / WPB;
    int w    = wg % WPB;
    if (b >= B) return;
    int lane = threadIdx.x & 31;

    int rpw = (N + WPB - 1) / WPB;       // 136
    int n0  = w * rpw;
    int n1  = min(N, n0 + rpw);

    const float4* rb = reinterpret_cast<const float4*>(g_r + b * HID);
    float4 rr[5], acc[5];
    #pragma unroll
    for (int k = 0; k < 5; k++) {
        rr[k]  = rb[lane + 32 * k];
        acc[k] = make_float4(0.f, 0.f, 0.f, 0.f);
    }

    float m = -1e30f, s = 0.f;
    const float4* base = reinterpret_cast<const float4*>(gh) + (size_t)b * N * (HID / 4);

    int n = n0;
    if ((n1 - n0) & 1) {                 // odd head: single row
        const float4* p = base + (size_t)n * (HID / 4);
        float4 hv[5];
        #pragma unroll
        for (int k = 0; k < 5; k++) hv[k] = __ldcs(p + lane + 32 * k);
        float d = 0.f;
        #pragma unroll
        for (int k = 0; k < 5; k++)
            d += hv[k].x * rr[k].x + hv[k].y * rr[k].y
               + hv[k].z * rr[k].z + hv[k].w * rr[k].w;
        #pragma unroll
        for (int o = 16; o > 0; o >>= 1) d += __shfl_xor_sync(0xffffffffu, d, o);
        m = d; s = 1.f;
        #pragma unroll
        for (int k = 0; k < 5; k++) acc[k] = hv[k];
        n++;
    }

    for (; n < n1; n += 2) {
        const float4* p0 = base + (size_t)n * (HID / 4);
        const float4* p1 = p0 + (HID / 4);
        float4 h0[5], h1[5];
        #pragma unroll
        for (int k = 0; k < 5; k++) h0[k] = __ldcs(p0 + lane + 32 * k);
        #pragma unroll
        for (int k = 0; k < 5; k++) h1[k] = __ldcs(p1 + lane + 32 * k);

        float d0 = 0.f, d1 = 0.f;
        #pragma unroll
        for (int k = 0; k < 5; k++) {
            d0 += h0[k].x * rr[k].x + h0[k].y * rr[k].y
                + h0[k].z * rr[k].z + h0[k].w * rr[k].w;
            d1 += h1[k].x * rr[k].x + h1[k].y * rr[k].y
                + h1[k].z * rr[k].z + h1[k].w * rr[k].w;
        }
        #pragma unroll
        for (int o = 16; o > 0; o >>= 1) {
            d0 += __shfl_xor_sync(0xffffffffu, d0, o);
            d1 += __shfl_xor_sync(0xffffffffu, d1, o);
        }

        float mn = fmaxf(d0, d1);
        if (mn > m) {                     // warp-uniform
            float c = __expf(m - mn);
            s *= c;
            #pragma unroll
            for (int k = 0; k < 5; k++) {
                acc[k].x *= c; acc[k].y *= c; acc[k].z *= c; acc[k].w *= c;
            }
            m = mn;
        }
        float w0 = __expf(d0 - m);
        float w1 = __expf(d1 - m);
        s += w0 + w1;
        #pragma unroll
        for (int k = 0; k < 5; k++) {
            acc[k].x += w0 * h0[k].x + w1 * h1[k].x;
            acc[k].y += w0 * h0[k].y + w1 * h1[k].y;
            acc[k].z += w0 * h0[k].z + w1 * h1[k].z;
            acc[k].w += w0 * h0[k].w + w1 * h1[k].w;
        }
    }

    float4* pa = reinterpret_cast<float4*>(g_pacc + (size_t)(b * WPB + w) * HID);
    #pragma unroll
    for (int k = 0; k < 5; k++) pa[lane + 32 * k] = acc[k];
    if (lane == 0) { g_pm[b * WPB + w] = m; g_ps[b * WPB + w] = s; }
}

// ---------------------------------------------------------------------------
// Kernel 3: pooled[b,h] = invS * sum_i wsm[i] * pacc[b,i,h]
// grid (B, 20) x 256: 32 h per block, 8 threads per h (19 partials, masked).
// wsm/M/S recomputed redundantly per block.
// ---------------------------------------------------------------------------
__global__ void __launch_bounds__(256) k_pooled(int dummy) {
    int b = blockIdx.x;
    int t = threadIdx.x;
    int lane = t & 31, wid = t >> 5;

    __shared__ float wsm[WPB];
    __shared__ float sred[8];
    __shared__ float sInvS;

    float pm = (t < WPB) ? g_pm[b * WPB + t] : -1e30f;
    float ps = (t < WPB) ? g_ps[b * WPB + t] : 0.f;

    float mv = pm;
    #pragma unroll
    for (int o = 16; o > 0; o >>= 1)
        mv = fmaxf(mv, __shfl_xor_sync(0xffffffffu, mv, o));
    if (lane == 0) sred[wid] = mv;
    __syncthreads();
    float M = sred[0];
    #pragma unroll
    for (int i = 1; i < 8; i++) M = fmaxf(M, sred[i]);
    __syncthreads();

    float w = (t < WPB) ? __expf(pm - M) : 0.f;
    if (t < WPB) wsm[t] = w;
    float sv = w * ps;
    #pragma unroll
    for (int o = 16; o > 0; o >>= 1) sv += __shfl_xor_sync(0xffffffffu, sv, o);
    if (lane == 0) sred[wid] = sv;
    __syncthreads();
    if (t == 0) {
        float S = 0.f;
        #pragma unroll
        for (int i = 0; i < 8; i++) S += sred[i];
        sInvS = 1.f / S;
    }
    __syncthreads();

    // 8 threads per h, 19 partials each (last group masked at 148)
    int h = blockIdx.y * 32 + (t & 31);
    int q = t >> 5;                        // 0..7
    const float* pa = g_pacc + (size_t)b * WPB * HID + h;

    float a = 0.f;
    int i0 = q * 19;
    int i1 = min(i0 + 19, WPB);
    #pragma unroll 4
    for (int i = i0; i < i1; i++)
        a += wsm[i] * pa[(size_t)i * HID];

    __shared__ float red[256];
    red[t] = a;
    __syncthreads();
    if (q == 0) {
        float tot = a;
        #pragma unroll
        for (int i = 1; i < 8; i++) tot += red[t + 32 * i];
        g_pooled[b * HID + h] = tot * sInvS;
    }
}

// ---------------------------------------------------------------------------
// Kernel 4: y[b,v] = dot(Wv[v,:], pooled[b,:])
// one warp per (b,v); v-major so 16 warps share each Wv row.
// ---------------------------------------------------------------------------
__global__ void __launch_bounds__(256) k_y(const float* __restrict__ Wv) {
    int gw   = blockIdx.x * 8 + (threadIdx.x >> 5);
    int lane = threadIdx.x & 31;
    int v = gw >> 4;
    int b = gw & 15;

    const float* wr = Wv + (size_t)v * HID;
    const float* pr = g_pooled + (size_t)b * HID;
    float s = 0.f;
    #pragma unroll
    for (int k = 0; k < HID / 32; k++) {
        int h = lane + 32 * k;
        s += wr[h] * pr[h];
    }
    #pragma unroll
    for (int o = 16; o > 0; o >>= 1) s += __shfl_xor_sync(0xffffffffu, s, o);
    if (lane == 0) g_y[b * HID + v] = s;
}

// ---------------------------------------------------------------------------
// Kernel 5: LayerNorm over 640. grid=B, block=640.
// ---------------------------------------------------------------------------
__device__ __forceinline__ float block_sum_640(float v, float* sred, int t) {
    int lane = t & 31, wid = t >> 5;
    #pragma unroll
    for (int o = 16; o > 0; o >>= 1) v += __shfl_xor_sync(0xffffffffu, v, o);
    if (lane == 0) sred[wid] = v;
    __syncthreads();
    if (wid == 0) {
        float x = (lane < 20) ? sred[lane] : 0.f;
        #pragma unroll
        for (int o = 16; o > 0; o >>= 1) x += __shfl_xor_sync(0xffffffffu, x, o);
        if (lane == 0) sred[0] = x;
    }
    __syncthreads();
    float r = sred[0];
    __syncthreads();
    return r;
}

__global__ void __launch_bounds__(640) k_ln(const float* __restrict__ gamma,
                                            const float* __restrict__ beta,
                                            float* __restrict__ out) {
    int b = blockIdx.x;
    int t = threadIdx.x;
    __shared__ float sred[32];

    float x = g_y[b * HID + t];
    float mean = block_sum_640(x, sred, t) * (1.f / HID);
    float dx = x - mean;
    float var = block_sum_640(dx * dx, sred, t) * (1.f / HID);
    out[b * HID + t] = dx * rsqrtf(var + 1e-5f) * gamma[t] + beta[t];
}

// ---------------------------------------------------------------------------
extern "C" void kernel_launch(void* const* d_in, const int* in_sizes, int n_in,
                              void* d_out, int out_size) {
    const float* gh    = (const float*)d_in[0];
    const float* pos   = (const float*)d_in[1];
    const float* Wq    = (const float*)d_in[2];
    const float* Wk    = (const float*)d_in[3];
    const float* Wv    = (const float*)d_in[4];
    const float* gamma = (const float*)d_in[5];
    const float* beta  = (const float*)d_in[6];
    float* out = (float*)d_out;

    int B = in_sizes[1] / HID;             // 16
    int N = in_sizes[0] / (B * HID);       // 20000
    float scale = 1.0f / sqrtf((float)ADIM);

    k_q<<<(B * ADIM) / 8, 256>>>(pos, Wq);            // 256 blocks
    k_r<<<dim3(B, 5), 512>>>(Wk, scale);              // 80 blocks

    int blocks = (B * WPB) / 8;            // 296 blocks = 2/SM
    k_pass1<<<blocks, 256>>>(gh, B, N);

    k_pooled<<<dim3(B, 20), 256>>>(0);                // 320 blocks
    k_y<<<(B * HID) / 8, 256>>>(Wv);                  // 1280 blocks
    k_ln<<<B, HID>>>(gamma, beta, out);
}